// round 6
// baseline (speedup 1.0000x reference)
#include <cuda_runtime.h>

#define NS 8
#define NC 128
#define KT 32
#define KF 16
#define FREQ 256
#define NFW 15
#define THR 15.0f
#define LPRE 431
#define NPOT 6400
#define MARGIN 0.05f

#define TP 33
#define RROW_OFF  14224
#define RROW2_OFF 21120
#define S_OFF     28016
#define X2_OFF    34416
#define SMEM_F    40816          /* 163,264 bytes */
/* fallback overlays (Rrow region is dead by then) */
#define SIDX_OFF  14224
#define HIST_OFF  17424
#define BST_OFF   17680

__device__ int      g_pool[NS * NFW * NC];
__device__ unsigned g_done;

__global__ __launch_bounds__(512, 1)
void spyke_kernel(const float* __restrict__ X, const float* __restrict__ W,
                  int* __restrict__ out)
{
    extern __shared__ float sm[];
    float*          tile  = sm;
    float*          Rrow  = sm + RROW_OFF;
    float*          Rrow2 = sm + RROW2_OFF;
    float*          Sarr  = sm + S_OFF;
    float*          X2arr = sm + X2_OFF;
    unsigned short* sidx  = (unsigned short*)(sm + SIDX_OFF);
    int*            hist  = (int*)(sm + HIST_OFF);
    int*            bst   = (int*)(sm + BST_OFF);

    __shared__ unsigned long long s_maxkey;
    __shared__ unsigned s_pool[4], s_amb[4];
    __shared__ int s_sig_i, s_smin_i, s_smax_i, s_fb, s_acnt, s_last, s_any, s_key;
    __shared__ float s_smin, s_scale, s_inv;
    __shared__ float s_cw[128], s_cb[128];
    __shared__ int s_alist[128];

    const int s = blockIdx.x / NFW, fwin = blockIdx.x % NFW;
    const int tid = threadIdx.x, col0 = fwin * 16, sec = s * 400;

    if (tid == 0) { s_maxkey = 0ULL; s_sig_i = 0; }
    if (tid < 4)  { s_pool[tid] = 0u; s_amb[tid] = 0u; }

    // ---- stage X window ----
    for (int i = tid; i < LPRE * 31; i += 512) {
        int r = i / 31, c = i - r * 31;
        tile[r * TP + c] = X[(sec + r) * FREQ + col0 + c];
    }
    __syncthreads();

    // ---- row sliding sums/sumsq over kf-window of 16 ----
    if (tid < LPRE) {
        float a = 0.f, a2 = 0.f;
        for (int c = 0; c < 16; ++c) { float x = tile[tid*TP + c]; a += x; a2 += x*x; }
        Rrow[tid*16] = a; Rrow2[tid*16] = a2;
        for (int f = 1; f < 16; ++f) {
            float xo = tile[tid*TP + f - 1], xn = tile[tid*TP + f + 15];
            a += xn - xo; a2 += xn*xn - xo*xo;
            Rrow[tid*16 + f] = a; Rrow2[tid*16 + f] = a2;
        }
    }
    __syncthreads();

    // ---- column sliding over kt-window of 32: S, Sx2; argmax + var-max ----
    if (tid < 320) {
        int f = tid / 20, t0 = (tid % 20) * 20;
        float a = 0.f, a2 = 0.f;
        for (int k = 0; k < 32; ++k) { a += Rrow[(t0+k)*16+f]; a2 += Rrow2[(t0+k)*16+f]; }
        unsigned long long lkey = 0ULL;
        float lsig = 0.f;
        for (int t = t0; t < t0 + 20; ++t) {
            int p = t*16 + f;
            Sarr[p] = a; X2arr[p] = a2;
            unsigned long long key = ((unsigned long long)__float_as_uint(a) << 13) | (unsigned)p;
            if (key > lkey) lkey = key;
            lsig = fmaxf(lsig, a2 - a*a*(1.0f/512.0f));
            if (t <= 398) {
                a  += Rrow[(t+32)*16+f]  - Rrow[t*16+f];
                a2 += Rrow2[(t+32)*16+f] - Rrow2[t*16+f];
            }
        }
        atomicMax(&s_maxkey, lkey);
        atomicMax(&s_sig_i, __float_as_int(fmaxf(lsig, 0.f)));
    }
    __syncthreads();

    const unsigned long long mk = s_maxkey;
    const float Smax = __uint_as_float((unsigned)(mk >> 13));
    const int   pstar = (int)(mk & 8191ULL);
    const float sigN  = sqrtf(fmaxf(X2arr[pstar] - Smax*Smax*(1.0f/512.0f), 0.f));
    const float sigMax = sqrtf(__int_as_float(s_sig_i));

    // ---- per-channel analytic test: 4 threads per channel reduce Sw, Sw2 ----
    {
        const int c = tid >> 2, q = tid & 3;
        const float4* Wc = (const float4*)(W + ((size_t)s * NC + c) * 512) + q * 32;
        float wsum = 0.f, wsq = 0.f;
        #pragma unroll 8
        for (int k = 0; k < 32; ++k) {
            float4 v = Wc[k];
            wsum += (v.x + v.y) + (v.z + v.w);
            wsq  += (v.x*v.x + v.y*v.y) + (v.z*v.z + v.w*v.w);
        }
        wsum += __shfl_xor_sync(0xffffffffu, wsum, 1);
        wsum += __shfl_xor_sync(0xffffffffu, wsum, 2);
        wsq  += __shfl_xor_sync(0xffffffffu, wsq, 1);
        wsq  += __shfl_xor_sync(0xffffffffu, wsq, 2);
        if (q == 0) {
            float Bn = sqrtf(fmaxf(wsq - wsum*wsum*(1.0f/512.0f), 0.f));
            s_cw[c] = wsum; s_cb[c] = Bn;
            float base = wsum * Smax * (1.0f/512.0f);
            unsigned bit = 1u << (c & 31);
            if (base - Bn*sigN >= THR + MARGIN)            atomicOr(&s_pool[c >> 5], bit);
            else if (base + Bn*sigMax >= THR - MARGIN)     atomicOr(&s_amb[c >> 5], bit);
            /* else provably below THR everywhere -> pool stays 0 */
        }
    }
    __syncthreads();
    if (tid == 0) {
        s_fb = (s_amb[0] | s_amb[1] | s_amb[2] | s_amb[3]) != 0u;
        s_smin_i = 0x7f7fffff; s_smax_i = 0; s_acnt = 0;
    }
    __syncthreads();

    // ================= rare fallback: exact evaluation of ambiguous channels ====
    if (s_fb) {
        // min/max of S for bucketing
        float lmin = 1e30f, lmax = -1e30f;
        for (int p = tid; p < NPOT; p += 512) {
            float v = Sarr[p];
            lmin = fminf(lmin, v); lmax = fmaxf(lmax, v);
        }
        atomicMin(&s_smin_i, __float_as_int(lmin));
        atomicMax(&s_smax_i, __float_as_int(lmax));
        if (tid < 256) hist[tid] = 0;
        __syncthreads();
        if (tid == 0) {
            float smin = __int_as_float(s_smin_i), smax = __int_as_float(s_smax_i);
            float inv = fmaxf(smax - smin, 1e-9f) * (1.0f/255.0f);
            s_smin = smin; s_inv = inv; s_scale = 1.0f / inv;
        }
        __syncthreads();
        for (int p = tid; p < NPOT; p += 512) {
            int b = (int)((Sarr[p] - s_smin) * s_scale);
            b = b < 0 ? 0 : (b > 255 ? 255 : b);
            atomicAdd(&hist[255 - b], 1);
        }
        __syncthreads();
        if (tid < 32) {
            int loc[8], ssum = 0;
            #pragma unroll
            for (int k = 0; k < 8; ++k) { loc[k] = ssum; ssum += hist[tid*8 + k]; }
            int excl = ssum;
            for (int d = 1; d < 32; d <<= 1) {
                int v = __shfl_up_sync(0xffffffffu, excl, d);
                if ((int)tid >= d) excl += v;
            }
            excl -= ssum;
            #pragma unroll
            for (int k = 0; k < 8; ++k) bst[tid*8 + k] = excl + loc[k];
        }
        __syncthreads();
        if (tid < 256) hist[tid] = bst[tid];
        __syncthreads();
        for (int p = tid; p < NPOT; p += 512) {
            int b = (int)((Sarr[p] - s_smin) * s_scale);
            b = b < 0 ? 0 : (b > 255 ? 255 : b);
            sidx[atomicAdd(&hist[255 - b], 1)] = (unsigned short)p;
        }
        if (tid < 128 && ((s_amb[tid >> 5] >> (tid & 31)) & 1u))
            s_alist[atomicAdd(&s_acnt, 1)] = tid;
        __syncthreads();

        // warp-per-channel descending scan
        const int wid = tid >> 5, lane = tid & 31;
        for (int ai = wid; ai < s_acnt; ai += 16) {
            const int c = s_alist[ai];
            const float cw = s_cw[c], cbn = s_cb[c];
            // lane owns kt = lane: 16 weights
            const float4* wr4 = (const float4*)(W + ((size_t)s * NC + c) * 512 + lane * 16);
            float4 w0 = wr4[0], w1 = wr4[1], w2 = wr4[2], w3 = wr4[3];
            int fired = 0;
            for (int rank = 0; rank < NPOT; ++rank) {
                int p = sidx[rank];
                float S = Sarr[p];
                int b = (int)((S - s_smin) * s_scale);
                b = b < 0 ? 0 : (b > 255 ? 255 : b);
                float hi = s_smin + (float)(b + 1) * s_inv;
                if (cw * hi * (1.0f/512.0f) + cbn * sigMax < THR - MARGIN) break; // dead
                float base = cw * S * (1.0f/512.0f);
                float sn = sqrtf(fmaxf(X2arr[p] - S*S*(1.0f/512.0f), 0.f));
                if (base - cbn*sn >= THR + MARGIN) { fired = 1; break; }
                if (base + cbn*sn <  THR - MARGIN) continue;
                // exact dot product
                int t = p >> 4, f = p & 15;
                const float* xr = tile + (t + lane) * TP + f;
                float a = w0.x*xr[0] + w0.y*xr[1] + w0.z*xr[2] + w0.w*xr[3]
                        + w1.x*xr[4] + w1.y*xr[5] + w1.z*xr[6] + w1.w*xr[7]
                        + w2.x*xr[8] + w2.y*xr[9] + w2.z*xr[10]+ w2.w*xr[11]
                        + w3.x*xr[12]+ w3.y*xr[13]+ w3.z*xr[14]+ w3.w*xr[15];
                #pragma unroll
                for (int d = 16; d; d >>= 1) a += __shfl_xor_sync(0xffffffffu, a, d);
                if (a >= THR) { fired = 1; break; }
            }
            if (fired && lane == 0) atomicOr(&s_pool[c >> 5], 1u << (c & 31));
        }
        __syncthreads();
    }

    if (tid < 128)
        g_pool[(s * NFW + fwin) * NC + tid] =
            (int)((s_pool[tid >> 5] >> (tid & 31)) & 1u);

    // ---- fused winner reduction (last CTA) ----
    __threadfence();
    __syncthreads();
    if (tid == 0) s_last = (atomicAdd(&g_done, 1u) == gridDim.x - 1u);
    __syncthreads();
    if (!s_last) return;
    __threadfence();

    unsigned char* mbuf = (unsigned char*)sm;
    if (tid == 0) { s_any = 0; s_key = -1; }
    __syncthreads();

    int localany = 0;
    for (int cell = tid; cell < NC * NFW; cell += 512) {
        int cc = cell / NFW, f = cell % NFW;
        unsigned mask = 0; int cnt = 0;
        #pragma unroll
        for (int ss = 0; ss < NS; ++ss) {
            int b = g_pool[(ss * NFW + f) * NC + cc];
            mask |= (unsigned)b << ss; cnt += b;
        }
        int e = 8 - cnt; e = e < 0 ? 0 : (e > 7 ? 7 : e);
        int val = (int)((mask >> e) & 1u);
        mbuf[cell] = (unsigned char)((cnt << 1) | val);
        if (cnt > 0 && val > 0) localany = 1;
    }
    if (localany) atomicOr(&s_any, 1);
    __syncthreads();

    const int v = s_any * 8;
    for (int cell = tid; cell < NC * NFW; cell += 512) {
        int d = mbuf[cell];
        int total = (d >> 1) * ((d & 1) + v);
        atomicMax(&s_key, (total << 11) | (2047 - cell));
    }
    __syncthreads();

    if (tid == 0) {
        int key = s_key, total = key >> 11, cell = 2047 - (key & 2047);
        out[0] = total ? (cell / NFW) : -1;
        g_done = 0;
    }
}

extern "C" void kernel_launch(void* const* d_in, const int* in_sizes, int n_in,
                              void* d_out, int out_size)
{
    (void)n_in; (void)out_size;
    const float* X = (const float*)d_in[0];
    const float* W = (const float*)d_in[1];
    if (in_sizes[0] == NS * NC * KT * KF) { const float* t = X; X = W; W = t; }

    const size_t smem = (size_t)SMEM_F * sizeof(float);
    cudaFuncSetAttribute(spyke_kernel,
                         cudaFuncAttributeMaxDynamicSharedMemorySize, (int)smem);
    spyke_kernel<<<NS * NFW, 512, smem>>>(X, W, (int*)d_out);
}